// round 3
// baseline (speedup 1.0000x reference)
#include <cuda_runtime.h>
#include <cstdint>

#define B_    4
#define KL    128
#define XL    4096
#define DIM   256
#define H_    8
#define HD    32
#define PB    8
#define NDIS  66
#define TDIM  768           // 3*DIM
#define SCALE 0.17677669529663687f
#define NMASK (B_ * H_ * XL * KL)   // 16,777,216 elements

// ---------------- scratch (device globals: no allocs allowed) ----------------
__device__ float    g_QKVx[B_ * XL * TDIM];
__device__ float    g_QKVk[B_ * KL * TDIM];
__device__ float    g_S[(size_t)B_ * H_ * KL * XL];
__device__ float    g_oriP[8 * B_ * H_ * KL * PB];     // per-x-slice partials (deterministic)
__device__ int      g_mo[B_ * H_ * KL];
__device__ uint8_t  g_maskC[(size_t)NMASK];            // canonical u8 mask (b,h,x,k)
__device__ uint8_t  g_maskT[(size_t)NMASK];            // transposed (b,h,k,x)
__device__ float    g_part[B_ * H_ * 8 * KL * 34];
__device__ float    g_preK[B_ * KL * DIM];
__device__ float    g_preX[B_ * XL * DIM];
__device__ unsigned g_flags;                            // mask dtype probe

// ---------------- mask dtype probe ----------------
__global__ void det_reset() { if (threadIdx.x == 0) g_flags = 0u; }

// Scan the first 1M 32-bit words (4MB — safe even if the buffer is u8/16MB).
__global__ void det_scan(const unsigned* __restrict__ w)
{
    int i = blockIdx.x * blockDim.x + threadIdx.x;
    unsigned v = w[i];
    unsigned f = 0;
    if (v == 0x3F800000u) f |= 1u;                       // float 1.0
    else if (v != 0u && v != 1u) f |= 2u;                // impossible for int32 0/1
    // warp-combine to cut atomics
    for (int o = 16; o > 0; o >>= 1) f |= __shfl_xor_sync(0xffffffffu, f, o);
    if ((threadIdx.x & 31) == 0 && f) atomicOr(&g_flags, f);
}

// canonicalize mask -> u8 {0,1}; 4 elements per thread
__global__ void conv_mask(const void* __restrict__ m)
{
    unsigned flags = g_flags;
    int mode = (flags & 1u) ? 2 : ((flags & 2u) ? 0 : 1);  // 0=u8 1=i32 2=f32
    int i = (blockIdx.x * blockDim.x + threadIdx.x) * 4;
    if (i >= NMASK) return;
    uchar4 o;
    if (mode == 0) {
        uchar4 v = *(const uchar4*)((const uint8_t*)m + i);
        o.x = v.x != 0; o.y = v.y != 0; o.z = v.z != 0; o.w = v.w != 0;
    } else if (mode == 1) {
        int4 v = *(const int4*)((const int*)m + i);
        o.x = v.x != 0; o.y = v.y != 0; o.z = v.z != 0; o.w = v.w != 0;
    } else {
        float4 v = *(const float4*)((const float*)m + i);
        o.x = v.x != 0.f; o.y = v.y != 0.f; o.z = v.z != 0.f; o.w = v.w != 0.f;
    }
    *(uchar4*)&g_maskC[i] = o;
}

// ---------------- SGEMM: C(MxN) = A(MxK) @ B(KxN) [+ bias] ----------------
__global__ __launch_bounds__(256) void sgemm128(
    const float* __restrict__ A, const float* __restrict__ Bm,
    const float* __restrict__ bias, float* __restrict__ C,
    int M, int N, int K)
{
    const int BM = 128, BN = 128, BK = 8, TM = 8, TN = 8;
    __shared__ float As[BK * BM];
    __shared__ float Bs[BK * BN];
    int tid = threadIdx.x;
    int cRow = blockIdx.y, cCol = blockIdx.x;
    const float* Ap = A + (size_t)cRow * BM * K;
    const float* Bp = Bm + cCol * BN;
    float* Cp = C + (size_t)cRow * BM * N + cCol * BN;

    int innerRowA = tid >> 1, innerColA = tid & 1;
    int innerRowB = tid >> 5, innerColB = tid & 31;
    int threadRow = tid >> 4, threadCol = tid & 15;

    float acc[TM * TN];
#pragma unroll
    for (int i = 0; i < TM * TN; i++) acc[i] = 0.f;
    float regM[TM], regN[TN];

    for (int k0 = 0; k0 < K; k0 += BK) {
        float4 a4 = *(const float4*)&Ap[(size_t)innerRowA * K + k0 + innerColA * 4];
        As[(innerColA * 4 + 0) * BM + innerRowA] = a4.x;
        As[(innerColA * 4 + 1) * BM + innerRowA] = a4.y;
        As[(innerColA * 4 + 2) * BM + innerRowA] = a4.z;
        As[(innerColA * 4 + 3) * BM + innerRowA] = a4.w;
        *(float4*)&Bs[innerRowB * BN + innerColB * 4] =
            *(const float4*)&Bp[(size_t)(k0 + innerRowB) * N + innerColB * 4];
        __syncthreads();
#pragma unroll
        for (int kk = 0; kk < BK; kk++) {
#pragma unroll
            for (int i = 0; i < TM; i++) regM[i] = As[kk * BM + threadRow * TM + i];
#pragma unroll
            for (int j = 0; j < TN; j++) regN[j] = Bs[kk * BN + threadCol * TN + j];
#pragma unroll
            for (int i = 0; i < TM; i++)
#pragma unroll
                for (int j = 0; j < TN; j++) acc[i * TN + j] += regM[i] * regN[j];
        }
        __syncthreads();
    }
#pragma unroll
    for (int i = 0; i < TM; i++) {
        int r = threadRow * TM + i;
#pragma unroll
        for (int j = 0; j < TN; j += 4) {
            int cidx = threadCol * TN + j;
            float4 v;
            v.x = acc[i * TN + j + 0];
            v.y = acc[i * TN + j + 1];
            v.z = acc[i * TN + j + 2];
            v.w = acc[i * TN + j + 3];
            if (bias) {
                v.x += bias[cCol * BN + cidx + 0];
                v.y += bias[cCol * BN + cidx + 1];
                v.z += bias[cCol * BN + cidx + 2];
                v.w += bias[cCol * BN + cidx + 3];
            }
            *(float4*)&Cp[(size_t)r * N + cidx] = v;
        }
    }
}

// ---------------- mask transpose: (b,h,x,k) -> (b,h,k,x) ----------------
__global__ void transpose_mask()
{
    __shared__ uint8_t tile[32][33];
    int bh = blockIdx.z;
    int x0 = blockIdx.x * 32, k0 = blockIdx.y * 32;
    int tx = threadIdx.x, ty = threadIdx.y;
#pragma unroll
    for (int i = ty; i < 32; i += 8)
        tile[i][tx] = g_maskC[((size_t)bh * XL + x0 + i) * KL + k0 + tx];
    __syncthreads();
#pragma unroll
    for (int i = ty; i < 32; i += 8)
        g_maskT[((size_t)bh * KL + k0 + i) * XL + x0 + tx] = tile[tx][i];
}

// ---------------- K2: kernel->x scores + orientation bins ----------------
// grid (XL/512, H, B), block 128 (thread = k)
__global__ __launch_bounds__(128) void k2_scores(const int* __restrict__ polar)
{
    int k = threadIdx.x;
    int xc = blockIdx.x, h = blockIdx.y, b = blockIdx.z;
    int bh = b * H_ + h;
    int xbase = xc * 512;
    __shared__ float kx_sh[64 * 32];

    float4 kq4[8];
    const float4* kqp = (const float4*)&g_QKVk[((size_t)(b * KL + k)) * TDIM + h * HD];
#pragma unroll
    for (int i = 0; i < 8; i++) kq4[i] = kqp[i];

    float bins[8];
#pragma unroll
    for (int o = 0; o < 8; o++) bins[o] = 0.f;

    float* Srow = &g_S[((size_t)bh * KL + k) * XL];
    const int* prow = &polar[((size_t)b * KL + k) * XL];

    for (int c = 0; c < 8; c++) {
        int xs = xbase + c * 64;
        __syncthreads();
        for (int g = threadIdx.x; g < 512; g += 128) {
            int row = g >> 3, c4 = g & 7;
            ((float4*)kx_sh)[g] =
                *(const float4*)&g_QKVx[((size_t)(b * XL + xs + row)) * TDIM + DIM + h * HD + c4 * 4];
        }
        __syncthreads();
        for (int j0 = 0; j0 < 64; j0 += 4) {
            float s[4];
#pragma unroll
            for (int jj = 0; jj < 4; jj++) {
                const float4* kx4 = (const float4*)&kx_sh[(j0 + jj) * 32];
                float a = 0.f;
#pragma unroll
                for (int d = 0; d < 8; d++) {
                    float4 v = kx4[d];
                    a += v.x * kq4[d].x + v.y * kq4[d].y + v.z * kq4[d].z + v.w * kq4[d].w;
                }
                s[jj] = a * SCALE;
            }
            *(float4*)&Srow[xs + j0] = make_float4(s[0], s[1], s[2], s[3]);
            int4 pp = *(const int4*)&prow[xs + j0];
            int pa[4] = {pp.x, pp.y, pp.z, pp.w};
#pragma unroll
            for (int jj = 0; jj < 4; jj++) {
                float as = fabsf(s[jj]);
#pragma unroll
                for (int o = 0; o < 8; o++) bins[o] += (pa[jj] == o) ? as : 0.f;
            }
        }
    }
    // deterministic: per-slice partial, reduced in fixed order later
    float* orow = &g_oriP[((size_t)xc * B_ * H_ * KL + bh * KL + k) * 8];
#pragma unroll
    for (int o = 0; o < 8; o++) orow[o] = bins[o];
}

// ---------------- K2c: reduce slices + argmax (first max) ----------------
__global__ void k2_argmax()
{
    int idx = blockIdx.x * blockDim.x + threadIdx.x;
    if (idx >= B_ * H_ * KL) return;
    float s[8];
#pragma unroll
    for (int o = 0; o < 8; o++) s[o] = 0.f;
#pragma unroll
    for (int xc = 0; xc < 8; xc++) {
        const float* p = &g_oriP[((size_t)xc * B_ * H_ * KL + idx) * 8];
#pragma unroll
        for (int o = 0; o < 8; o++) s[o] += p[o];
    }
    int best = 0;
    float bv = s[0];
#pragma unroll
    for (int p = 1; p < 8; p++)
        if (s[p] > bv) { bv = s[p]; best = p; }
    g_mo[idx] = best;
}

// ---------------- K3: kernel->x attention (online softmax, x-split) -------
__global__ __launch_bounds__(128) void k3_kattn(
    const int* __restrict__ rd, const int* __restrict__ polar,
    const float* __restrict__ dis_embed, const float* __restrict__ polar_emb)
{
    int k = threadIdx.x;
    int xs = blockIdx.x, h = blockIdx.y, b = blockIdx.z;
    int bh = b * H_ + h;
    __shared__ float V_sh[64 * 32];
    __shared__ float de_sh[NDIS];
    __shared__ float pe_sh[8];
    if (k < NDIS) de_sh[k] = dis_embed[k * H_ + h];
    if (k < 8) pe_sh[k] = polar_emb[k];
    int mo = g_mo[bh * KL + k];

    const float*   Srow = &g_S[((size_t)bh * KL + k) * XL];
    const int*     rrow = &rd[((size_t)b * KL + k) * XL];
    const int*     prow = &polar[((size_t)b * KL + k) * XL];
    const uint8_t* mrow = &g_maskT[((size_t)bh * KL + k) * XL];

    float m = -1e30f, l = 0.f;
    float acc[32];
#pragma unroll
    for (int d = 0; d < 32; d++) acc[d] = 0.f;

    int xbase = xs * 512;
    for (int c = 0; c < 8; c++) {
        int x0 = xbase + c * 64;
        __syncthreads();
        for (int g = threadIdx.x; g < 512; g += 128) {
            int row = g >> 3, c4 = g & 7;
            ((float4*)V_sh)[g] =
                *(const float4*)&g_QKVx[((size_t)(b * XL + x0 + row)) * TDIM + 2 * DIM + h * HD + c4 * 4];
        }
        __syncthreads();
        for (int j0 = 0; j0 < 64; j0 += 4) {
            float4 s4 = *(const float4*)&Srow[x0 + j0];
            int4 r4 = *(const int4*)&rrow[x0 + j0];
            int4 p4 = *(const int4*)&prow[x0 + j0];
            uchar4 mk4 = *(const uchar4*)&mrow[x0 + j0];
            float sv[4] = {s4.x, s4.y, s4.z, s4.w};
            int   rv[4] = {r4.x, r4.y, r4.z, r4.w};
            int   pv[4] = {p4.x, p4.y, p4.z, p4.w};
            uint8_t mv[4] = {mk4.x, mk4.y, mk4.z, mk4.w};
#pragma unroll
            for (int jj = 0; jj < 4; jj++) {
                float t = (mv[jj] ? -1e6f : sv[jj]) + de_sh[rv[jj]] + pe_sh[(pv[jj] - mo) & 7];
                float mn = fmaxf(m, t);
                float eo = __expf(m - mn);
                float w  = __expf(t - mn);
                l = l * eo + w;
                m = mn;
                const float4* vp = (const float4*)&V_sh[(j0 + jj) * 32];
#pragma unroll
                for (int d = 0; d < 8; d++) {
                    float4 v = vp[d];
                    acc[d * 4 + 0] = acc[d * 4 + 0] * eo + w * v.x;
                    acc[d * 4 + 1] = acc[d * 4 + 1] * eo + w * v.y;
                    acc[d * 4 + 2] = acc[d * 4 + 2] * eo + w * v.z;
                    acc[d * 4 + 3] = acc[d * 4 + 3] * eo + w * v.w;
                }
            }
        }
    }
    float* pp = &g_part[(((size_t)bh * 8 + xs) * KL + k) * 34];
    pp[0] = m;
    pp[1] = l;
#pragma unroll
    for (int d = 0; d < 32; d++) pp[2 + d] = acc[d];
}

// ---------------- K3c: combine x-splits -> preK ----------------
__global__ void k3_combine()
{
    int idx = blockIdx.x * blockDim.x + threadIdx.x;
    if (idx >= B_ * H_ * KL) return;
    int k = idx % KL, bh = idx / KL;
    int h = bh % H_, b = bh / H_;
    const int SSTR = KL * 34;
    const float* base = &g_part[((size_t)bh * 8) * SSTR + k * 34];
    float M = -1e30f;
#pragma unroll
    for (int s = 0; s < 8; s++) M = fmaxf(M, base[s * SSTR]);
    float es[8], L = 0.f;
#pragma unroll
    for (int s = 0; s < 8; s++) {
        es[s] = __expf(base[s * SSTR] - M);
        L += base[s * SSTR + 1] * es[s];
    }
    float invL = 1.f / L;
    float* out = &g_preK[((size_t)b * KL + k) * DIM + h * HD];
#pragma unroll
    for (int d = 0; d < 32; d++) {
        float a = 0.f;
#pragma unroll
        for (int s = 0; s < 8; s++) a += base[s * SSTR + 2 + d] * es[s];
        out[d] = a * invL;
    }
}

// ---------------- K4: x->kernel attention (fully fused) ----------------
__global__ __launch_bounds__(256) void k4_xattn(
    const int* __restrict__ rd, const int* __restrict__ polar,
    const float* __restrict__ dis_embed, const float* __restrict__ polar_emb)
{
    __shared__ float kk_sh[KL * HD];
    __shared__ float kv_sh[KL * HD];
    __shared__ float de_sh[NDIS];
    __shared__ float pe_sh[8];
    __shared__ int   mo_sh[KL];
    int tid = threadIdx.x;
    int xc = blockIdx.x, h = blockIdx.y, b = blockIdx.z;
    int bh = b * H_ + h;

    for (int g = tid; g < KL * HD / 4; g += 256) {
        int row = g >> 3, c4 = g & 7;
        ((float4*)kk_sh)[g] =
            *(const float4*)&g_QKVk[((size_t)(b * KL + row)) * TDIM + DIM + h * HD + c4 * 4];
        ((float4*)kv_sh)[g] =
            *(const float4*)&g_QKVk[((size_t)(b * KL + row)) * TDIM + 2 * DIM + h * HD + c4 * 4];
    }
    if (tid < NDIS) de_sh[tid] = dis_embed[tid * H_ + h];
    if (tid < 8) pe_sh[tid] = polar_emb[tid];
    if (tid < KL) mo_sh[tid] = g_mo[bh * KL + tid];
    __syncthreads();

    int x = xc * 256 + tid;
    float4 q4[8];
    const float4* qp = (const float4*)&g_QKVx[((size_t)(b * XL + x)) * TDIM + h * HD];
#pragma unroll
    for (int i = 0; i < 8; i++) q4[i] = qp[i];
    const uint8_t* mrow = &g_maskC[((size_t)bh * XL + x) * KL];

    float m = -1e30f, l = 0.f;
    float acc[32];
#pragma unroll
    for (int d = 0; d < 32; d++) acc[d] = 0.f;

    for (int k0 = 0; k0 < KL; k0 += 4) {
        uchar4 mk4 = *(const uchar4*)&mrow[k0];
        uint8_t mv[4] = {mk4.x, mk4.y, mk4.z, mk4.w};
#pragma unroll
        for (int ki = 0; ki < 4; ki++) {
            int kidx = k0 + ki;
            const float4* kkp = (const float4*)&kk_sh[kidx * HD];
            float s = 0.f;
#pragma unroll
            for (int d = 0; d < 8; d++) {
                float4 a = kkp[d];
                s += a.x * q4[d].x + a.y * q4[d].y + a.z * q4[d].z + a.w * q4[d].w;
            }
            s *= SCALE;
            int rv = rd[((size_t)b * KL + kidx) * XL + x];
            int pv = polar[((size_t)b * KL + kidx) * XL + x];
            float t = (mv[ki] ? -1e9f : s) + de_sh[rv] + pe_sh[(pv - mo_sh[kidx]) & 7];
            float mn = fmaxf(m, t);
            float eo = __expf(m - mn);
            float w  = __expf(t - mn);
            l = l * eo + w;
            m = mn;
            const float4* vp = (const float4*)&kv_sh[kidx * HD];
#pragma unroll
            for (int d = 0; d < 8; d++) {
                float4 v = vp[d];
                acc[d * 4 + 0] = acc[d * 4 + 0] * eo + w * v.x;
                acc[d * 4 + 1] = acc[d * 4 + 1] * eo + w * v.y;
                acc[d * 4 + 2] = acc[d * 4 + 2] * eo + w * v.z;
                acc[d * 4 + 3] = acc[d * 4 + 3] * eo + w * v.w;
            }
        }
    }
    float invl = 1.f / l;
    float* out = &g_preX[((size_t)(b * XL + x)) * DIM + h * HD];
#pragma unroll
    for (int d = 0; d < 8; d++) {
        float4 v;
        v.x = acc[d * 4 + 0] * invl;
        v.y = acc[d * 4 + 1] * invl;
        v.z = acc[d * 4 + 2] * invl;
        v.w = acc[d * 4 + 3] * invl;
        *(float4*)&out[d * 4] = v;
    }
}

// ---------------- host launcher ----------------
extern "C" void kernel_launch(void* const* d_in, const int* in_sizes, int n_in,
                              void* d_out, int out_size)
{
    const float* x     = (const float*)d_in[0];
    const float* kern  = (const float*)d_in[1];
    const int*   rd    = (const int*)d_in[2];
    const int*   polar = (const int*)d_in[3];
    const void*  mask  = d_in[4];
    const float* Wqkv  = (const float*)d_in[5];
    const float* dis   = (const float*)d_in[6];
    const float* pemb  = (const float*)d_in[7];
    const float* Wproj = (const float*)d_in[8];
    const float* bproj = (const float*)d_in[9];
    float* out = (float*)d_out;

    float* pQKVx; cudaGetSymbolAddress((void**)&pQKVx, g_QKVx);
    float* pQKVk; cudaGetSymbolAddress((void**)&pQKVk, g_QKVk);
    float* pPreX; cudaGetSymbolAddress((void**)&pPreX, g_preX);
    float* pPreK; cudaGetSymbolAddress((void**)&pPreK, g_preK);

    // mask dtype probe + canonicalization
    det_reset<<<1, 32>>>();
    det_scan<<<4096, 256>>>((const unsigned*)mask);
    conv_mask<<<(NMASK / 4 + 255) / 256, 256>>>(mask);
    transpose_mask<<<dim3(XL / 32, KL / 32, B_ * H_), dim3(32, 8)>>>();

    // QKV projections
    sgemm128<<<dim3(TDIM / 128, (B_ * XL) / 128), 256>>>(x, Wqkv, nullptr, pQKVx, B_ * XL, TDIM, DIM);
    sgemm128<<<dim3(TDIM / 128, (B_ * KL) / 128), 256>>>(kern, Wqkv, nullptr, pQKVk, B_ * KL, TDIM, DIM);

    // kernel->x scores + orientation
    k2_scores<<<dim3(XL / 512, H_, B_), 128>>>(polar);
    k2_argmax<<<(B_ * H_ * KL + 255) / 256, 256>>>();

    // kernel->x attention
    k3_kattn<<<dim3(8, H_, B_), 128>>>(rd, polar, dis, pemb);
    k3_combine<<<(B_ * H_ * KL + 255) / 256, 256>>>();

    // x->kernel attention
    k4_xattn<<<dim3(XL / 256, H_, B_), 256>>>(rd, polar, dis, pemb);

    // output projections: x_out first, then k_out
    sgemm128<<<dim3(DIM / 128, (B_ * XL) / 128), 256>>>(pPreX, Wproj, bproj, out, B_ * XL, DIM, DIM);
    sgemm128<<<dim3(DIM / 128, (B_ * KL) / 128), 256>>>(pPreK, Wproj, bproj, out + (size_t)B_ * XL * DIM, B_ * KL, DIM, DIM);
}